// round 2
// baseline (speedup 1.0000x reference)
#include <cuda_runtime.h>
#include <math.h>

#define DIMN 2048
#define NH   16
#define HD   128
#define BSZ  2
#define SEQ  2048
#define ROWS (BSZ*SEQ)   // 4096

// Scratch buffers (allocation-free rule: __device__ globals)
__device__ float g_q[ROWS*DIMN];
__device__ float g_k[ROWS*DIMN];
__device__ float g_v[ROWS*DIMN];
__device__ float g_att[ROWS*DIMN];

// ---------------------------------------------------------------------------
// GEMM: C[M,N] = A[M,K] * B[N,K]^T   (A, B row-major; both K-contiguous)
// 128x128 block tile, BK=8, 256 threads, 8x8 per-thread microtile.
// ---------------------------------------------------------------------------
__global__ __launch_bounds__(256) void gemm_abt(const float* __restrict__ A,
                                                const float* __restrict__ B,
                                                float* __restrict__ C,
                                                int M, int N, int K)
{
    __shared__ float As[8][128];
    __shared__ float Bs[8][128];

    const int tid = threadIdx.x;
    const int ty  = tid >> 4;       // 0..15
    const int tx  = tid & 15;       // 0..15
    const int m0  = blockIdx.y * 128;
    const int n0  = blockIdx.x * 128;
    const int lrow = tid >> 1;      // 0..127
    const int lc4  = (tid & 1) * 4; // 0 or 4

    const float* Ap = A + (size_t)(m0 + lrow) * K + lc4;
    const float* Bp = B + (size_t)(n0 + lrow) * K + lc4;

    float acc[8][8];
    #pragma unroll
    for (int i = 0; i < 8; i++)
        #pragma unroll
        for (int j = 0; j < 8; j++) acc[i][j] = 0.f;

    for (int k0 = 0; k0 < K; k0 += 8) {
        float4 av = *(const float4*)(Ap + k0);
        float4 bv = *(const float4*)(Bp + k0);
        As[lc4+0][lrow] = av.x; As[lc4+1][lrow] = av.y;
        As[lc4+2][lrow] = av.z; As[lc4+3][lrow] = av.w;
        Bs[lc4+0][lrow] = bv.x; Bs[lc4+1][lrow] = bv.y;
        Bs[lc4+2][lrow] = bv.z; Bs[lc4+3][lrow] = bv.w;
        __syncthreads();

        #pragma unroll
        for (int kk = 0; kk < 8; kk++) {
            float a[8], b[8];
            *(float4*)(a)   = *(const float4*)&As[kk][ty*8];
            *(float4*)(a+4) = *(const float4*)&As[kk][ty*8+4];
            *(float4*)(b)   = *(const float4*)&Bs[kk][tx*8];
            *(float4*)(b+4) = *(const float4*)&Bs[kk][tx*8+4];
            #pragma unroll
            for (int i = 0; i < 8; i++)
                #pragma unroll
                for (int j = 0; j < 8; j++)
                    acc[i][j] = fmaf(a[i], b[j], acc[i][j]);
        }
        __syncthreads();
    }

    #pragma unroll
    for (int i = 0; i < 8; i++) {
        float* cp = C + (size_t)(m0 + ty*8 + i) * N + n0 + tx*8;
        float4 o0 = make_float4(acc[i][0], acc[i][1], acc[i][2], acc[i][3]);
        float4 o1 = make_float4(acc[i][4], acc[i][5], acc[i][6], acc[i][7]);
        *(float4*)(cp)     = o0;
        *(float4*)(cp + 4) = o1;
    }
}

// ---------------------------------------------------------------------------
// RoPE (interleaved pairs) applied in-place to Q and K.
// One thread per (row, pair); ROWS*1024 threads total.
// ---------------------------------------------------------------------------
__global__ __launch_bounds__(256) void rope_kernel(float* __restrict__ q,
                                                   float* __restrict__ k,
                                                   const float* __restrict__ fc,
                                                   const float* __restrict__ fs)
{
    int idx = blockIdx.x * blockDim.x + threadIdx.x;  // 0 .. ROWS*1024-1
    int row = idx >> 10;
    int pr  = idx & 1023;         // pair index within row (h*64 + p)
    int s   = row & (SEQ - 1);    // sequence position
    int p   = pr & 63;            // pair within head
    float c  = fc[s*64 + p];
    float sn = fs[s*64 + p];

    size_t off = (size_t)row * DIMN + pr * 2;

    float2 v = *(float2*)(q + off);
    float2 o;
    o.x = v.x * c - v.y * sn;
    o.y = v.x * sn + v.y * c;
    *(float2*)(q + off) = o;

    v = *(float2*)(k + off);
    o.x = v.x * c - v.y * sn;
    o.y = v.x * sn + v.y * c;
    *(float2*)(k + off) = o;
}

// ---------------------------------------------------------------------------
// Flash attention (causal, online softmax), fp32.
// Block = (64-query tile, head, batch). 256 threads (16x16).
// Thread owns S rows {ty+16i}, S cols {tx+16j}; O rows {ty+16i}, dims tx*8..+7.
// Smem: Qs[64][132], Ks[64][132] (reused as Ps[64][72]), Vs[64][132].
// ---------------------------------------------------------------------------
#define AT_P 132
#define AT_SMEM (3 * 64 * AT_P * 4)

__global__ __launch_bounds__(256) void attn_kernel()
{
    extern __shared__ float smf[];
    float* Qs = smf;
    float* Ks = smf + 64 * AT_P;
    float* Vs = smf + 2 * 64 * AT_P;

    const int tid = threadIdx.x;
    const int ty  = tid >> 4;
    const int tx  = tid & 15;
    const int qt  = blockIdx.x;     // query tile 0..31
    const int h   = blockIdx.y;
    const int b   = blockIdx.z;
    const int q0g = qt * 64;

    const float* Qg  = g_q + (size_t)(b*SEQ + q0g) * DIMN + h * HD;
    const float* Kg0 = g_k + (size_t)(b*SEQ) * DIMN + h * HD;
    const float* Vg0 = g_v + (size_t)(b*SEQ) * DIMN + h * HD;

    const float qscale = 0.08838834764831845f;  // 1/sqrt(128)

    // Load & pre-scale Q tile (64 x 128)
    #pragma unroll
    for (int it = 0; it < 8; it++) {
        int i = it * 256 + tid;
        int r = i >> 5;
        int c = (i & 31) * 4;
        float4 v = *(const float4*)(Qg + (size_t)r * DIMN + c);
        v.x *= qscale; v.y *= qscale; v.z *= qscale; v.w *= qscale;
        *(float4*)&Qs[r * AT_P + c] = v;
    }

    float mM[4], lS[4], acc[4][8];
    #pragma unroll
    for (int i = 0; i < 4; i++) {
        mM[i] = -1e30f; lS[i] = 0.f;
        #pragma unroll
        for (int j = 0; j < 8; j++) acc[i][j] = 0.f;
    }

    const float* qr[4];
    const float* kr[4];
    #pragma unroll
    for (int i = 0; i < 4; i++) qr[i] = &Qs[(ty + 16*i) * AT_P];
    #pragma unroll
    for (int j = 0; j < 4; j++) kr[j] = &Ks[(tx + 16*j) * AT_P];

    for (int kt = 0; kt <= qt; kt++) {
        const int k0g = kt * 64;
        __syncthreads();  // previous iteration done with Ks(Ps)/Vs

        // Load K, V tiles (64 x 128)
        #pragma unroll
        for (int it = 0; it < 8; it++) {
            int i = it * 256 + tid;
            int r = i >> 5;
            int c = (i & 31) * 4;
            *(float4*)&Ks[r * AT_P + c] =
                *(const float4*)(Kg0 + (size_t)(k0g + r) * DIMN + c);
            *(float4*)&Vs[r * AT_P + c] =
                *(const float4*)(Vg0 + (size_t)(k0g + r) * DIMN + c);
        }
        __syncthreads();

        // S = Q K^T
        float sv[4][4];
        #pragma unroll
        for (int i = 0; i < 4; i++)
            #pragma unroll
            for (int j = 0; j < 4; j++) sv[i][j] = 0.f;

        #pragma unroll 8
        for (int d = 0; d < HD; d++) {
            float a0 = qr[0][d], a1 = qr[1][d], a2 = qr[2][d], a3 = qr[3][d];
            float b0 = kr[0][d], b1 = kr[1][d], b2 = kr[2][d], b3 = kr[3][d];
            sv[0][0] = fmaf(a0,b0,sv[0][0]); sv[0][1] = fmaf(a0,b1,sv[0][1]);
            sv[0][2] = fmaf(a0,b2,sv[0][2]); sv[0][3] = fmaf(a0,b3,sv[0][3]);
            sv[1][0] = fmaf(a1,b0,sv[1][0]); sv[1][1] = fmaf(a1,b1,sv[1][1]);
            sv[1][2] = fmaf(a1,b2,sv[1][2]); sv[1][3] = fmaf(a1,b3,sv[1][3]);
            sv[2][0] = fmaf(a2,b0,sv[2][0]); sv[2][1] = fmaf(a2,b1,sv[2][1]);
            sv[2][2] = fmaf(a2,b2,sv[2][2]); sv[2][3] = fmaf(a2,b3,sv[2][3]);
            sv[3][0] = fmaf(a3,b0,sv[3][0]); sv[3][1] = fmaf(a3,b1,sv[3][1]);
            sv[3][2] = fmaf(a3,b2,sv[3][2]); sv[3][3] = fmaf(a3,b3,sv[3][3]);
        }

        // Causal mask (only the diagonal tile; k0g == q0g there)
        if (kt == qt) {
            #pragma unroll
            for (int i = 0; i < 4; i++)
                #pragma unroll
                for (int j = 0; j < 4; j++)
                    if (tx + 16*j > ty + 16*i) sv[i][j] = -1e30f;
        }

        // Online softmax per owned row (reduce over 16 tx lanes)
        float pf[4][4], fac[4];
        #pragma unroll
        for (int i = 0; i < 4; i++) {
            float rm = fmaxf(fmaxf(sv[i][0], sv[i][1]), fmaxf(sv[i][2], sv[i][3]));
            #pragma unroll
            for (int off = 8; off >= 1; off >>= 1)
                rm = fmaxf(rm, __shfl_xor_sync(0xffffffffu, rm, off));
            float mn = fmaxf(mM[i], rm);
            fac[i] = __expf(mM[i] - mn);
            float rs = 0.f;
            #pragma unroll
            for (int j = 0; j < 4; j++) {
                pf[i][j] = __expf(sv[i][j] - mn);
                rs += pf[i][j];
            }
            #pragma unroll
            for (int off = 8; off >= 1; off >>= 1)
                rs += __shfl_xor_sync(0xffffffffu, rs, off);
            lS[i] = lS[i] * fac[i] + rs;
            mM[i] = mn;
            #pragma unroll
            for (int j = 0; j < 8; j++) acc[i][j] *= fac[i];
        }

        __syncthreads();  // everyone done reading Ks

        // Store P tile into the K buffer region: Ps[64][72]
        float* Ps = Ks;
        #pragma unroll
        for (int i = 0; i < 4; i++)
            #pragma unroll
            for (int j = 0; j < 4; j++)
                Ps[(ty + 16*i) * 72 + (tx + 16*j)] = pf[i][j];
        __syncthreads();

        // O += P V
        #pragma unroll 4
        for (int k = 0; k < 64; k++) {
            float p0 = Ps[(ty      ) * 72 + k];
            float p1 = Ps[(ty + 16 ) * 72 + k];
            float p2 = Ps[(ty + 32 ) * 72 + k];
            float p3 = Ps[(ty + 48 ) * 72 + k];
            float4 v0 = *(const float4*)&Vs[k * AT_P + tx*8];
            float4 v1 = *(const float4*)&Vs[k * AT_P + tx*8 + 4];
            acc[0][0]=fmaf(p0,v0.x,acc[0][0]); acc[0][1]=fmaf(p0,v0.y,acc[0][1]);
            acc[0][2]=fmaf(p0,v0.z,acc[0][2]); acc[0][3]=fmaf(p0,v0.w,acc[0][3]);
            acc[0][4]=fmaf(p0,v1.x,acc[0][4]); acc[0][5]=fmaf(p0,v1.y,acc[0][5]);
            acc[0][6]=fmaf(p0,v1.z,acc[0][6]); acc[0][7]=fmaf(p0,v1.w,acc[0][7]);
            acc[1][0]=fmaf(p1,v0.x,acc[1][0]); acc[1][1]=fmaf(p1,v0.y,acc[1][1]);
            acc[1][2]=fmaf(p1,v0.z,acc[1][2]); acc[1][3]=fmaf(p1,v0.w,acc[1][3]);
            acc[1][4]=fmaf(p1,v1.x,acc[1][4]); acc[1][5]=fmaf(p1,v1.y,acc[1][5]);
            acc[1][6]=fmaf(p1,v1.z,acc[1][6]); acc[1][7]=fmaf(p1,v1.w,acc[1][7]);
            acc[2][0]=fmaf(p2,v0.x,acc[2][0]); acc[2][1]=fmaf(p2,v0.y,acc[2][1]);
            acc[2][2]=fmaf(p2,v0.z,acc[2][2]); acc[2][3]=fmaf(p2,v0.w,acc[2][3]);
            acc[2][4]=fmaf(p2,v1.x,acc[2][4]); acc[2][5]=fmaf(p2,v1.y,acc[2][5]);
            acc[2][6]=fmaf(p2,v1.z,acc[2][6]); acc[2][7]=fmaf(p2,v1.w,acc[2][7]);
            acc[3][0]=fmaf(p3,v0.x,acc[3][0]); acc[3][1]=fmaf(p3,v0.y,acc[3][1]);
            acc[3][2]=fmaf(p3,v0.z,acc[3][2]); acc[3][3]=fmaf(p3,v0.w,acc[3][3]);
            acc[3][4]=fmaf(p3,v1.x,acc[3][4]); acc[3][5]=fmaf(p3,v1.y,acc[3][5]);
            acc[3][6]=fmaf(p3,v1.z,acc[3][6]); acc[3][7]=fmaf(p3,v1.w,acc[3][7]);
        }
    }

    // Epilogue: normalize and write to g_att in (b, s, h*HD + d) layout
    float* Og = g_att + (size_t)(b*SEQ + q0g) * DIMN + h * HD;
    #pragma unroll
    for (int i = 0; i < 4; i++) {
        float inv = 1.f / lS[i];
        float4 o0 = make_float4(acc[i][0]*inv, acc[i][1]*inv, acc[i][2]*inv, acc[i][3]*inv);
        float4 o1 = make_float4(acc[i][4]*inv, acc[i][5]*inv, acc[i][6]*inv, acc[i][7]*inv);
        float* op = Og + (size_t)(ty + 16*i) * DIMN + tx*8;
        *(float4*)(op)     = o0;
        *(float4*)(op + 4) = o1;
    }
}

// ---------------------------------------------------------------------------
// Launch: Q/K/V projections -> RoPE -> flash attention -> output projection
// ---------------------------------------------------------------------------
extern "C" void kernel_launch(void* const* d_in, const int* in_sizes, int n_in,
                              void* d_out, int out_size)
{
    const float* x  = (const float*)d_in[0];
    // d_in[1] = start_pos (always 0), d_in[4] = mask (implicit causal) — unused
    const float* fc = (const float*)d_in[2];
    const float* fs = (const float*)d_in[3];
    const float* wq = (const float*)d_in[5];
    const float* wk = (const float*)d_in[6];
    const float* wv = (const float*)d_in[7];
    const float* wo = (const float*)d_in[8];
    float* out = (float*)d_out;

    float *q, *k, *v, *att;
    cudaGetSymbolAddress((void**)&q,   g_q);
    cudaGetSymbolAddress((void**)&k,   g_k);
    cudaGetSymbolAddress((void**)&v,   g_v);
    cudaGetSymbolAddress((void**)&att, g_att);

    cudaFuncSetAttribute(attn_kernel,
                         cudaFuncAttributeMaxDynamicSharedMemorySize, AT_SMEM);

    dim3 gg(DIMN/128, ROWS/128);   // (16, 32)
    gemm_abt<<<gg, 256>>>(x, wq, q, ROWS, DIMN, DIMN);
    gemm_abt<<<gg, 256>>>(x, wk, k, ROWS, DIMN, DIMN);
    gemm_abt<<<gg, 256>>>(x, wv, v, ROWS, DIMN, DIMN);

    rope_kernel<<<(ROWS*1024)/256, 256>>>(q, k, fc, fs);

    dim3 ga(SEQ/64, NH, BSZ);
    attn_kernel<<<ga, 256, AT_SMEM>>>();

    gemm_abt<<<gg, 256>>>(att, wo, out, ROWS, DIMN, DIMN);
}

// round 5
// speedup vs baseline: 1.9850x; 1.9850x over previous
#include <cuda_runtime.h>
#include <math.h>

#define DIMN 2048
#define NH   16
#define HD   128
#define BSZ  2
#define SEQ  2048
#define ROWS (BSZ*SEQ)   // 4096

// Scratch buffers (allocation-free rule: __device__ globals)
__device__ float g_q[ROWS*DIMN];
__device__ float g_k[ROWS*DIMN];
__device__ float g_v[ROWS*DIMN];
__device__ float g_att[ROWS*DIMN];

// ---------------------------------------------------------------------------
// TF32 tensor-core GEMM: C[M,N] = A[M,K] * B[N,K]^T  (both K-contiguous)
// 128x128 block tile, BK=32, 256 threads (8 warps, 2x4 warp grid, 64x32/warp),
// mma.sync.m16n8k8.tf32. Smem padded to stride 36 -> conflict-free fragments.
// ---------------------------------------------------------------------------
#define BM 128
#define BN 128
#define BK 32

__device__ __forceinline__ unsigned f2tf32(float x) {
    unsigned r;
    asm("cvt.rna.tf32.f32 %0, %1;" : "=r"(r) : "f"(x));
    return r;
}

__device__ __forceinline__ void mma_tf32(float c[4],
                                         const unsigned a[4],
                                         const unsigned b[2]) {
    asm("mma.sync.aligned.m16n8k8.row.col.f32.tf32.tf32.f32 "
        "{%0,%1,%2,%3}, {%4,%5,%6,%7}, {%8,%9}, {%0,%1,%2,%3};"
        : "+f"(c[0]), "+f"(c[1]), "+f"(c[2]), "+f"(c[3])
        : "r"(a[0]), "r"(a[1]), "r"(a[2]), "r"(a[3]),
          "r"(b[0]), "r"(b[1]));
}

__global__ __launch_bounds__(256, 1) void gemm_tf32(const float* __restrict__ A,
                                                    const float* __restrict__ B,
                                                    float* __restrict__ C,
                                                    int M, int N, int K)
{
    __shared__ unsigned As[BM][BK + 4];   // stride 36
    __shared__ unsigned Bs[BN][BK + 4];

    const int tid  = threadIdx.x;
    const int wid  = tid >> 5;
    const int lane = tid & 31;
    const int lq   = lane >> 2;           // 0..7
    const int lr   = lane & 3;            // 0..3
    const int wm   = (wid >> 2) * 64;     // warp m offset (0/64)
    const int wn   = (wid & 3) * 32;      // warp n offset (0/32/64/96)
    const int m0   = blockIdx.y * BM;
    const int n0   = blockIdx.x * BN;

    const int lrow = tid >> 3;             // 0..31
    const int lc4  = (tid & 7) * 4;        // 0..28

    float c[4][4][4];
    #pragma unroll
    for (int mt = 0; mt < 4; mt++)
        #pragma unroll
        for (int nt = 0; nt < 4; nt++)
            #pragma unroll
            for (int r = 0; r < 4; r++) c[mt][nt][r] = 0.f;

    const float* Ap = A + (size_t)(m0 + lrow) * K + lc4;
    const float* Bp = B + (size_t)(n0 + lrow) * K + lc4;

    // Prologue: load stage 0
    float4 ra[4], rb[4];
    #pragma unroll
    for (int it = 0; it < 4; it++) {
        ra[it] = *(const float4*)(Ap + (size_t)(it * 32) * K);
        rb[it] = *(const float4*)(Bp + (size_t)(it * 32) * K);
    }

    for (int k0 = 0; k0 < K; k0 += BK) {
        // Store current stage (converted to tf32 bits)
        #pragma unroll
        for (int it = 0; it < 4; it++) {
            int row = it * 32 + lrow;
            uint4 av = make_uint4(f2tf32(ra[it].x), f2tf32(ra[it].y),
                                  f2tf32(ra[it].z), f2tf32(ra[it].w));
            uint4 bv = make_uint4(f2tf32(rb[it].x), f2tf32(rb[it].y),
                                  f2tf32(rb[it].z), f2tf32(rb[it].w));
            *(uint4*)&As[row][lc4] = av;
            *(uint4*)&Bs[row][lc4] = bv;
        }
        __syncthreads();

        // Prefetch next stage
        if (k0 + BK < K) {
            #pragma unroll
            for (int it = 0; it < 4; it++) {
                ra[it] = *(const float4*)(Ap + (size_t)(it * 32) * K + k0 + BK);
                rb[it] = *(const float4*)(Bp + (size_t)(it * 32) * K + k0 + BK);
            }
        }

        // Compute 4 k8 steps
        #pragma unroll
        for (int ks = 0; ks < 4; ks++) {
            const int kb = ks * 8;
            unsigned af[4][4], bf[4][2];
            #pragma unroll
            for (int mt = 0; mt < 4; mt++) {
                int r = wm + mt * 16;
                af[mt][0] = As[r + lq    ][kb + lr    ];
                af[mt][1] = As[r + lq + 8][kb + lr    ];
                af[mt][2] = As[r + lq    ][kb + lr + 4];
                af[mt][3] = As[r + lq + 8][kb + lr + 4];
            }
            #pragma unroll
            for (int nt = 0; nt < 4; nt++) {
                int cn = wn + nt * 8;
                bf[nt][0] = Bs[cn + lq][kb + lr    ];
                bf[nt][1] = Bs[cn + lq][kb + lr + 4];
            }
            #pragma unroll
            for (int mt = 0; mt < 4; mt++)
                #pragma unroll
                for (int nt = 0; nt < 4; nt++)
                    mma_tf32(c[mt][nt], af[mt], bf[nt]);
        }
        __syncthreads();
    }

    // Epilogue
    #pragma unroll
    for (int mt = 0; mt < 4; mt++) {
        int row = m0 + wm + mt * 16 + lq;
        #pragma unroll
        for (int nt = 0; nt < 4; nt++) {
            int col = n0 + wn + nt * 8 + lr * 2;
            *(float2*)(C + (size_t)row * N + col)       = make_float2(c[mt][nt][0], c[mt][nt][1]);
            *(float2*)(C + (size_t)(row + 8) * N + col) = make_float2(c[mt][nt][2], c[mt][nt][3]);
        }
    }
}

// ---------------------------------------------------------------------------
// RoPE (interleaved pairs) applied in-place to Q and K.
// ---------------------------------------------------------------------------
__global__ __launch_bounds__(256) void rope_kernel(float* __restrict__ q,
                                                   float* __restrict__ k,
                                                   const float* __restrict__ fc,
                                                   const float* __restrict__ fs)
{
    int idx = blockIdx.x * blockDim.x + threadIdx.x;
    int row = idx >> 10;
    int pr  = idx & 1023;
    int s   = row & (SEQ - 1);
    int p   = pr & 63;
    float c  = fc[s*64 + p];
    float sn = fs[s*64 + p];

    size_t off = (size_t)row * DIMN + pr * 2;

    float2 v = *(float2*)(q + off);
    float2 o;
    o.x = v.x * c - v.y * sn;
    o.y = v.x * sn + v.y * c;
    *(float2*)(q + off) = o;

    v = *(float2*)(k + off);
    o.x = v.x * c - v.y * sn;
    o.y = v.x * sn + v.y * c;
    *(float2*)(k + off) = o;
}

// ---------------------------------------------------------------------------
// Flash attention (causal, online softmax), fp32. Unchanged from R1.
// ---------------------------------------------------------------------------
#define AT_P 132
#define AT_SMEM (3 * 64 * AT_P * 4)

__global__ __launch_bounds__(256) void attn_kernel()
{
    extern __shared__ float smf[];
    float* Qs = smf;
    float* Ks = smf + 64 * AT_P;
    float* Vs = smf + 2 * 64 * AT_P;

    const int tid = threadIdx.x;
    const int ty  = tid >> 4;
    const int tx  = tid & 15;
    const int qt  = blockIdx.x;
    const int h   = blockIdx.y;
    const int b   = blockIdx.z;
    const int q0g = qt * 64;

    const float* Qg  = g_q + (size_t)(b*SEQ + q0g) * DIMN + h * HD;
    const float* Kg0 = g_k + (size_t)(b*SEQ) * DIMN + h * HD;
    const float* Vg0 = g_v + (size_t)(b*SEQ) * DIMN + h * HD;

    const float qscale = 0.08838834764831845f;

    #pragma unroll
    for (int it = 0; it < 8; it++) {
        int i = it * 256 + tid;
        int r = i >> 5;
        int cc = (i & 31) * 4;
        float4 v = *(const float4*)(Qg + (size_t)r * DIMN + cc);
        v.x *= qscale; v.y *= qscale; v.z *= qscale; v.w *= qscale;
        *(float4*)&Qs[r * AT_P + cc] = v;
    }

    float mM[4], lS[4], acc[4][8];
    #pragma unroll
    for (int i = 0; i < 4; i++) {
        mM[i] = -1e30f; lS[i] = 0.f;
        #pragma unroll
        for (int j = 0; j < 8; j++) acc[i][j] = 0.f;
    }

    const float* qr[4];
    const float* kr[4];
    #pragma unroll
    for (int i = 0; i < 4; i++) qr[i] = &Qs[(ty + 16*i) * AT_P];
    #pragma unroll
    for (int j = 0; j < 4; j++) kr[j] = &Ks[(tx + 16*j) * AT_P];

    for (int kt = 0; kt <= qt; kt++) {
        const int k0g = kt * 64;
        __syncthreads();

        #pragma unroll
        for (int it = 0; it < 8; it++) {
            int i = it * 256 + tid;
            int r = i >> 5;
            int cc = (i & 31) * 4;
            *(float4*)&Ks[r * AT_P + cc] =
                *(const float4*)(Kg0 + (size_t)(k0g + r) * DIMN + cc);
            *(float4*)&Vs[r * AT_P + cc] =
                *(const float4*)(Vg0 + (size_t)(k0g + r) * DIMN + cc);
        }
        __syncthreads();

        float sv[4][4];
        #pragma unroll
        for (int i = 0; i < 4; i++)
            #pragma unroll
            for (int j = 0; j < 4; j++) sv[i][j] = 0.f;

        #pragma unroll 8
        for (int d = 0; d < HD; d++) {
            float a0 = qr[0][d], a1 = qr[1][d], a2 = qr[2][d], a3 = qr[3][d];
            float b0 = kr[0][d], b1 = kr[1][d], b2 = kr[2][d], b3 = kr[3][d];
            sv[0][0] = fmaf(a0,b0,sv[0][0]); sv[0][1] = fmaf(a0,b1,sv[0][1]);
            sv[0][2] = fmaf(a0,b2,sv[0][2]); sv[0][3] = fmaf(a0,b3,sv[0][3]);
            sv[1][0] = fmaf(a1,b0,sv[1][0]); sv[1][1] = fmaf(a1,b1,sv[1][1]);
            sv[1][2] = fmaf(a1,b2,sv[1][2]); sv[1][3] = fmaf(a1,b3,sv[1][3]);
            sv[2][0] = fmaf(a2,b0,sv[2][0]); sv[2][1] = fmaf(a2,b1,sv[2][1]);
            sv[2][2] = fmaf(a2,b2,sv[2][2]); sv[2][3] = fmaf(a2,b3,sv[2][3]);
            sv[3][0] = fmaf(a3,b0,sv[3][0]); sv[3][1] = fmaf(a3,b1,sv[3][1]);
            sv[3][2] = fmaf(a3,b2,sv[3][2]); sv[3][3] = fmaf(a3,b3,sv[3][3]);
        }

        if (kt == qt) {
            #pragma unroll
            for (int i = 0; i < 4; i++)
                #pragma unroll
                for (int j = 0; j < 4; j++)
                    if (tx + 16*j > ty + 16*i) sv[i][j] = -1e30f;
        }

        float pf[4][4], fac[4];
        #pragma unroll
        for (int i = 0; i < 4; i++) {
            float rm = fmaxf(fmaxf(sv[i][0], sv[i][1]), fmaxf(sv[i][2], sv[i][3]));
            #pragma unroll
            for (int off = 8; off >= 1; off >>= 1)
                rm = fmaxf(rm, __shfl_xor_sync(0xffffffffu, rm, off));
            float mn = fmaxf(mM[i], rm);
            fac[i] = __expf(mM[i] - mn);
            float rs = 0.f;
            #pragma unroll
            for (int j = 0; j < 4; j++) {
                pf[i][j] = __expf(sv[i][j] - mn);
                rs += pf[i][j];
            }
            #pragma unroll
            for (int off = 8; off >= 1; off >>= 1)
                rs += __shfl_xor_sync(0xffffffffu, rs, off);
            lS[i] = lS[i] * fac[i] + rs;
            mM[i] = mn;
            #pragma unroll
            for (int j = 0; j < 8; j++) acc[i][j] *= fac[i];
        }

        __syncthreads();

        float* Ps = Ks;
        #pragma unroll
        for (int i = 0; i < 4; i++)
            #pragma unroll
            for (int j = 0; j < 4; j++)
                Ps[(ty + 16*i) * 72 + (tx + 16*j)] = pf[i][j];
        __syncthreads();

        #pragma unroll 4
        for (int k = 0; k < 64; k++) {
            float p0 = Ps[(ty      ) * 72 + k];
            float p1 = Ps[(ty + 16 ) * 72 + k];
            float p2 = Ps[(ty + 32 ) * 72 + k];
            float p3 = Ps[(ty + 48 ) * 72 + k];
            float4 v0 = *(const float4*)&Vs[k * AT_P + tx*8];
            float4 v1 = *(const float4*)&Vs[k * AT_P + tx*8 + 4];
            acc[0][0]=fmaf(p0,v0.x,acc[0][0]); acc[0][1]=fmaf(p0,v0.y,acc[0][1]);
            acc[0][2]=fmaf(p0,v0.z,acc[0][2]); acc[0][3]=fmaf(p0,v0.w,acc[0][3]);
            acc[0][4]=fmaf(p0,v1.x,acc[0][4]); acc[0][5]=fmaf(p0,v1.y,acc[0][5]);
            acc[0][6]=fmaf(p0,v1.z,acc[0][6]); acc[0][7]=fmaf(p0,v1.w,acc[0][7]);
            acc[1][0]=fmaf(p1,v0.x,acc[1][0]); acc[1][1]=fmaf(p1,v0.y,acc[1][1]);
            acc[1][2]=fmaf(p1,v0.z,acc[1][2]); acc[1][3]=fmaf(p1,v0.w,acc[1][3]);
            acc[1][4]=fmaf(p1,v1.x,acc[1][4]); acc[1][5]=fmaf(p1,v1.y,acc[1][5]);
            acc[1][6]=fmaf(p1,v1.z,acc[1][6]); acc[1][7]=fmaf(p1,v1.w,acc[1][7]);
            acc[2][0]=fmaf(p2,v0.x,acc[2][0]); acc[2][1]=fmaf(p2,v0.y,acc[2][1]);
            acc[2][2]=fmaf(p2,v0.z,acc[2][2]); acc[2][3]=fmaf(p2,v0.w,acc[2][3]);
            acc[2][4]=fmaf(p2,v1.x,acc[2][4]); acc[2][5]=fmaf(p2,v1.y,acc[2][5]);
            acc[2][6]=fmaf(p2,v1.z,acc[2][6]); acc[2][7]=fmaf(p2,v1.w,acc[2][7]);
            acc[3][0]=fmaf(p3,v0.x,acc[3][0]); acc[3][1]=fmaf(p3,v0.y,acc[3][1]);
            acc[3][2]=fmaf(p3,v0.z,acc[3][2]); acc[3][3]=fmaf(p3,v0.w,acc[3][3]);
            acc[3][4]=fmaf(p3,v1.x,acc[3][4]); acc[3][5]=fmaf(p3,v1.y,acc[3][5]);
            acc[3][6]=fmaf(p3,v1.z,acc[3][6]); acc[3][7]=fmaf(p3,v1.w,acc[3][7]);
        }
    }

    float* Og = g_att + (size_t)(b*SEQ + q0g) * DIMN + h * HD;
    #pragma unroll
    for (int i = 0; i < 4; i++) {
        float inv = 1.f / lS[i];
        float4 o0 = make_float4(acc[i][0]*inv, acc[i][1]*inv, acc[i][2]*inv, acc[i][3]*inv);
        float4 o1 = make_float4(acc[i][4]*inv, acc[i][5]*inv, acc[i][6]*inv, acc[i][7]*inv);
        float* op = Og + (size_t)(ty + 16*i) * DIMN + tx*8;
        *(float4*)(op)     = o0;
        *(float4*)(op + 4) = o1;
    }
}

// ---------------------------------------------------------------------------
// Launch
// ---------------------------------------------------------------------------
extern "C" void kernel_launch(void* const* d_in, const int* in_sizes, int n_in,
                              void* d_out, int out_size)
{
    const float* x  = (const float*)d_in[0];
    const float* fc = (const float*)d_in[2];
    const float* fs = (const float*)d_in[3];
    const float* wq = (const float*)d_in[5];
    const float* wk = (const float*)d_in[6];
    const float* wv = (const float*)d_in[7];
    const float* wo = (const float*)d_in[8];
    float* out = (float*)d_out;

    float *q, *k, *v, *att;
    cudaGetSymbolAddress((void**)&q,   g_q);
    cudaGetSymbolAddress((void**)&k,   g_k);
    cudaGetSymbolAddress((void**)&v,   g_v);
    cudaGetSymbolAddress((void**)&att, g_att);

    cudaFuncSetAttribute(attn_kernel,
                         cudaFuncAttributeMaxDynamicSharedMemorySize, AT_SMEM);

    dim3 gg(DIMN/128, ROWS/128);   // (16, 32)
    gemm_tf32<<<gg, 256>>>(x, wq, q, ROWS, DIMN, DIMN);
    gemm_tf32<<<gg, 256>>>(x, wk, k, ROWS, DIMN, DIMN);
    gemm_tf32<<<gg, 256>>>(x, wv, v, ROWS, DIMN, DIMN);

    rope_kernel<<<(ROWS*1024)/256, 256>>>(q, k, fc, fs);

    dim3 ga(SEQ/64, NH, BSZ);
    attn_kernel<<<ga, 256, AT_SMEM>>>();

    gemm_tf32<<<gg, 256>>>(att, wo, out, ROWS, DIMN, DIMN);
}

// round 7
// speedup vs baseline: 3.0155x; 1.5191x over previous
#include <cuda_runtime.h>
#include <math.h>

#define DIMN 2048
#define NH   16
#define HD   128
#define BSZ  2
#define SEQ  2048
#define ROWS (BSZ*SEQ)   // 4096

// Scratch buffers (allocation-free rule: __device__ globals)
__device__ float g_q[ROWS*DIMN];
__device__ float g_k[ROWS*DIMN];
__device__ float g_v[ROWS*DIMN];
__device__ float g_att[ROWS*DIMN];

__device__ __forceinline__ unsigned f2tf32(float x) {
    unsigned r;
    asm("cvt.rna.tf32.f32 %0, %1;" : "=r"(r) : "f"(x));
    return r;
}

__device__ __forceinline__ void mma_tf32(float c[4],
                                         const unsigned a[4],
                                         const unsigned b[2]) {
    asm("mma.sync.aligned.m16n8k8.row.col.f32.tf32.tf32.f32 "
        "{%0,%1,%2,%3}, {%4,%5,%6,%7}, {%8,%9}, {%0,%1,%2,%3};"
        : "+f"(c[0]), "+f"(c[1]), "+f"(c[2]), "+f"(c[3])
        : "r"(a[0]), "r"(a[1]), "r"(a[2]), "r"(a[3]),
          "r"(b[0]), "r"(b[1]));
}

// ---------------------------------------------------------------------------
// TF32 tensor-core GEMM: C[M,N] = A[M,K] * B[N,K]^T  (unchanged from R5)
// ---------------------------------------------------------------------------
#define BM 128
#define BN 128
#define BK 32

__global__ __launch_bounds__(256, 1) void gemm_tf32(const float* __restrict__ A,
                                                    const float* __restrict__ B,
                                                    float* __restrict__ C,
                                                    int M, int N, int K)
{
    __shared__ unsigned As[BM][BK + 4];
    __shared__ unsigned Bs[BN][BK + 4];

    const int tid  = threadIdx.x;
    const int wid  = tid >> 5;
    const int lane = tid & 31;
    const int lq   = lane >> 2;
    const int lr   = lane & 3;
    const int wm   = (wid >> 2) * 64;
    const int wn   = (wid & 3) * 32;
    const int m0   = blockIdx.y * BM;
    const int n0   = blockIdx.x * BN;

    const int lrow = tid >> 3;
    const int lc4  = (tid & 7) * 4;

    float c[4][4][4];
    #pragma unroll
    for (int mt = 0; mt < 4; mt++)
        #pragma unroll
        for (int nt = 0; nt < 4; nt++)
            #pragma unroll
            for (int r = 0; r < 4; r++) c[mt][nt][r] = 0.f;

    const float* Ap = A + (size_t)(m0 + lrow) * K + lc4;
    const float* Bp = B + (size_t)(n0 + lrow) * K + lc4;

    float4 ra[4], rb[4];
    #pragma unroll
    for (int it = 0; it < 4; it++) {
        ra[it] = *(const float4*)(Ap + (size_t)(it * 32) * K);
        rb[it] = *(const float4*)(Bp + (size_t)(it * 32) * K);
    }

    for (int k0 = 0; k0 < K; k0 += BK) {
        #pragma unroll
        for (int it = 0; it < 4; it++) {
            int row = it * 32 + lrow;
            uint4 av = make_uint4(f2tf32(ra[it].x), f2tf32(ra[it].y),
                                  f2tf32(ra[it].z), f2tf32(ra[it].w));
            uint4 bv = make_uint4(f2tf32(rb[it].x), f2tf32(rb[it].y),
                                  f2tf32(rb[it].z), f2tf32(rb[it].w));
            *(uint4*)&As[row][lc4] = av;
            *(uint4*)&Bs[row][lc4] = bv;
        }
        __syncthreads();

        if (k0 + BK < K) {
            #pragma unroll
            for (int it = 0; it < 4; it++) {
                ra[it] = *(const float4*)(Ap + (size_t)(it * 32) * K + k0 + BK);
                rb[it] = *(const float4*)(Bp + (size_t)(it * 32) * K + k0 + BK);
            }
        }

        #pragma unroll
        for (int ks = 0; ks < 4; ks++) {
            const int kb = ks * 8;
            unsigned af[4][4], bf[4][2];
            #pragma unroll
            for (int mt = 0; mt < 4; mt++) {
                int r = wm + mt * 16;
                af[mt][0] = As[r + lq    ][kb + lr    ];
                af[mt][1] = As[r + lq + 8][kb + lr    ];
                af[mt][2] = As[r + lq    ][kb + lr + 4];
                af[mt][3] = As[r + lq + 8][kb + lr + 4];
            }
            #pragma unroll
            for (int nt = 0; nt < 4; nt++) {
                int cn = wn + nt * 8;
                bf[nt][0] = Bs[cn + lq][kb + lr    ];
                bf[nt][1] = Bs[cn + lq][kb + lr + 4];
            }
            #pragma unroll
            for (int mt = 0; mt < 4; mt++)
                #pragma unroll
                for (int nt = 0; nt < 4; nt++)
                    mma_tf32(c[mt][nt], af[mt], bf[nt]);
        }
        __syncthreads();
    }

    #pragma unroll
    for (int mt = 0; mt < 4; mt++) {
        int row = m0 + wm + mt * 16 + lq;
        #pragma unroll
        for (int nt = 0; nt < 4; nt++) {
            int col = n0 + wn + nt * 8 + lr * 2;
            *(float2*)(C + (size_t)row * N + col)       = make_float2(c[mt][nt][0], c[mt][nt][1]);
            *(float2*)(C + (size_t)(row + 8) * N + col) = make_float2(c[mt][nt][2], c[mt][nt][3]);
        }
    }
}

// ---------------------------------------------------------------------------
// RoPE (unchanged)
// ---------------------------------------------------------------------------
__global__ __launch_bounds__(256) void rope_kernel(float* __restrict__ q,
                                                   float* __restrict__ k,
                                                   const float* __restrict__ fc,
                                                   const float* __restrict__ fs)
{
    int idx = blockIdx.x * blockDim.x + threadIdx.x;
    int row = idx >> 10;
    int pr  = idx & 1023;
    int s   = row & (SEQ - 1);
    int p   = pr & 63;
    float c  = fc[s*64 + p];
    float sn = fs[s*64 + p];

    size_t off = (size_t)row * DIMN + pr * 2;

    float2 v = *(float2*)(q + off);
    float2 o;
    o.x = v.x * c - v.y * sn;
    o.y = v.x * sn + v.y * c;
    *(float2*)(q + off) = o;

    v = *(float2*)(k + off);
    o.x = v.x * c - v.y * sn;
    o.y = v.x * sn + v.y * c;
    *(float2*)(k + off) = o;
}

// ---------------------------------------------------------------------------
// Tensor-core flash attention (causal, online softmax).
// 128-query tile per CTA, 8 warps (16 rows each), 64-key k-tiles.
// Q split hi+lo tf32 (exact Q); K, V single tf32.
// Smem: Qhi/Qlo 128x128 XOR-swizzled; K[64][132]; V[64][136]. 195KB, 1 CTA/SM.
// ---------------------------------------------------------------------------
#define KSTR 132
#define VSTR 136
#define AT_SMEM ((2*128*128 + 64*KSTR + 64*VSTR) * 4)

__global__ __launch_bounds__(256, 1) void attn_tc()
{
    extern __shared__ unsigned sm[];
    unsigned* Qhi = sm;
    unsigned* Qlo = sm + 128*128;
    unsigned* Ks  = sm + 2*128*128;
    unsigned* Vs  = Ks + 64*KSTR;

    const int tid  = threadIdx.x;
    const int wid  = tid >> 5;
    const int lane = tid & 31;
    const int lq   = lane >> 2;      // 0..7
    const int lr   = lane & 3;       // 0..3
    const int qt   = gridDim.x - 1 - blockIdx.x;   // heavy tiles first
    const int h    = blockIdx.y;
    const int b    = blockIdx.z;
    const int q0   = qt * 128;
    const int R0   = wid * 16;

    const float* Qg = g_q + (size_t)(b*SEQ + q0) * DIMN + h * HD;
    const float* Kg = g_k + (size_t)(b*SEQ) * DIMN + h * HD;
    const float* Vg = g_v + (size_t)(b*SEQ) * DIMN + h * HD;

    const float qsc = 0.08838834764831845f;  // 1/sqrt(128)

    // Load Q tile (128x128), scale, split into tf32 hi/lo, swizzled store
    #pragma unroll
    for (int it = 0; it < 16; it++) {
        int i  = it * 256 + tid;
        int r  = i >> 5;              // 0..127
        int c4 = (i & 31) * 4;        // 0..124
        float4 v = *(const float4*)(Qg + (size_t)r * DIMN + c4);
        v.x *= qsc; v.y *= qsc; v.z *= qsc; v.w *= qsc;
        unsigned h0 = f2tf32(v.x), h1 = f2tf32(v.y),
                 h2 = f2tf32(v.z), h3 = f2tf32(v.w);
        unsigned l0 = f2tf32(v.x - __uint_as_float(h0));
        unsigned l1 = f2tf32(v.y - __uint_as_float(h1));
        unsigned l2 = f2tf32(v.z - __uint_as_float(h2));
        unsigned l3 = f2tf32(v.w - __uint_as_float(h3));
        int blk = (c4 >> 2) ^ (r & 7);
        *(uint4*)&Qhi[r * 128 + blk * 4] = make_uint4(h0, h1, h2, h3);
        *(uint4*)&Qlo[r * 128 + blk * 4] = make_uint4(l0, l1, l2, l3);
    }

    float o[16][4];
    #pragma unroll
    for (int n = 0; n < 16; n++)
        #pragma unroll
        for (int r = 0; r < 4; r++) o[n][r] = 0.f;
    float m0r = -1e30f, m1r = -1e30f, l0r = 0.f, l1r = 0.f;

    const int nkt = 2 * qt + 2;
    for (int kt = 0; kt < nkt; kt++) {
        const int k0 = kt * 64;
        __syncthreads();   // prior iteration done with Ks/Vs (and Q written, kt=0)

        // Load K, V tiles (64x128), tf32-convert
        #pragma unroll
        for (int it = 0; it < 8; it++) {
            int i  = it * 256 + tid;
            int r  = i >> 5;
            int c4 = (i & 31) * 4;
            float4 kv = *(const float4*)(Kg + (size_t)(k0 + r) * DIMN + c4);
            float4 vv = *(const float4*)(Vg + (size_t)(k0 + r) * DIMN + c4);
            *(uint4*)&Ks[r * KSTR + c4] =
                make_uint4(f2tf32(kv.x), f2tf32(kv.y), f2tf32(kv.z), f2tf32(kv.w));
            *(uint4*)&Vs[r * VSTR + c4] =
                make_uint4(f2tf32(vv.x), f2tf32(vv.y), f2tf32(vv.z), f2tf32(vv.w));
        }
        __syncthreads();

        // S = Q K^T  (M=16/warp, N=64, K=128) with Q = hi + lo
        float s[8][4];
        #pragma unroll
        for (int j = 0; j < 8; j++)
            #pragma unroll
            for (int r = 0; r < 4; r++) s[j][r] = 0.f;

        #pragma unroll
        for (int ks = 0; ks < 16; ks++) {
            unsigned ah[4], al[4];
            int rA = (R0 + lq) * 128;
            int rB = (R0 + lq + 8) * 128;
            int blk0 = ((2*ks    ) ^ lq) * 4 + lr;
            int blk1 = ((2*ks + 1) ^ lq) * 4 + lr;
            ah[0] = Qhi[rA + blk0]; ah[1] = Qhi[rB + blk0];
            ah[2] = Qhi[rA + blk1]; ah[3] = Qhi[rB + blk1];
            al[0] = Qlo[rA + blk0]; al[1] = Qlo[rB + blk0];
            al[2] = Qlo[rA + blk1]; al[3] = Qlo[rB + blk1];
            #pragma unroll
            for (int j = 0; j < 8; j++) {
                unsigned bf[2];
                bf[0] = Ks[(8*j + lq) * KSTR + 8*ks + lr    ];
                bf[1] = Ks[(8*j + lq) * KSTR + 8*ks + lr + 4];
                mma_tf32(s[j], ah, bf);
                mma_tf32(s[j], al, bf);
            }
        }

        // Causal mask (tiles overlapping the diagonal)
        if (kt >= 2 * qt) {
            int grow0 = q0 + R0 + lq;
            int grow1 = grow0 + 8;
            #pragma unroll
            for (int j = 0; j < 8; j++) {
                int gc = k0 + 8*j + 2*lr;
                if (gc     > grow0) s[j][0] = -1e30f;
                if (gc + 1 > grow0) s[j][1] = -1e30f;
                if (gc     > grow1) s[j][2] = -1e30f;
                if (gc + 1 > grow1) s[j][3] = -1e30f;
            }
        }

        // Online softmax (rows lq and lq+8; 4 lanes/row -> xor 1,2)
        float mx0 = -1e30f, mx1 = -1e30f;
        #pragma unroll
        for (int j = 0; j < 8; j++) {
            mx0 = fmaxf(mx0, fmaxf(s[j][0], s[j][1]));
            mx1 = fmaxf(mx1, fmaxf(s[j][2], s[j][3]));
        }
        mx0 = fmaxf(mx0, __shfl_xor_sync(0xffffffffu, mx0, 1));
        mx0 = fmaxf(mx0, __shfl_xor_sync(0xffffffffu, mx0, 2));
        mx1 = fmaxf(mx1, __shfl_xor_sync(0xffffffffu, mx1, 1));
        mx1 = fmaxf(mx1, __shfl_xor_sync(0xffffffffu, mx1, 2));

        float mn0 = fmaxf(m0r, mx0), mn1 = fmaxf(m1r, mx1);
        float f0 = __expf(m0r - mn0), f1 = __expf(m1r - mn1);
        m0r = mn0; m1r = mn1;

        #pragma unroll
        for (int n = 0; n < 16; n++) {
            o[n][0] *= f0; o[n][1] *= f0;
            o[n][2] *= f1; o[n][3] *= f1;
        }

        float sum0 = 0.f, sum1 = 0.f;
        #pragma unroll
        for (int j = 0; j < 8; j++) {
            s[j][0] = __expf(s[j][0] - mn0);
            s[j][1] = __expf(s[j][1] - mn0);
            s[j][2] = __expf(s[j][2] - mn1);
            s[j][3] = __expf(s[j][3] - mn1);
            sum0 += s[j][0] + s[j][1];
            sum1 += s[j][2] + s[j][3];
        }
        sum0 += __shfl_xor_sync(0xffffffffu, sum0, 1);
        sum0 += __shfl_xor_sync(0xffffffffu, sum0, 2);
        sum1 += __shfl_xor_sync(0xffffffffu, sum1, 1);
        sum1 += __shfl_xor_sync(0xffffffffu, sum1, 2);
        l0r = l0r * f0 + sum0;
        l1r = l1r * f1 + sum1;

        // O += P V : transform P acc->A frag via shfl, B from Vs
        const int srcA = lq * 4 + (lr >> 1);
        const int srcB = srcA + 2;
        const bool odd = (lr & 1);
        #pragma unroll
        for (int j = 0; j < 8; j++) {
            float t0 = __shfl_sync(0xffffffffu, s[j][0], srcA);
            float t1 = __shfl_sync(0xffffffffu, s[j][1], srcA);
            float t2 = __shfl_sync(0xffffffffu, s[j][2], srcA);
            float t3 = __shfl_sync(0xffffffffu, s[j][3], srcA);
            float u0 = __shfl_sync(0xffffffffu, s[j][0], srcB);
            float u1 = __shfl_sync(0xffffffffu, s[j][1], srcB);
            float u2 = __shfl_sync(0xffffffffu, s[j][2], srcB);
            float u3 = __shfl_sync(0xffffffffu, s[j][3], srcB);
            unsigned pa[4];
            pa[0] = f2tf32(odd ? t1 : t0);
            pa[1] = f2tf32(odd ? t3 : t2);
            pa[2] = f2tf32(odd ? u1 : u0);
            pa[3] = f2tf32(odd ? u3 : u2);
            #pragma unroll
            for (int n = 0; n < 16; n++) {
                unsigned bf[2];
                bf[0] = Vs[(8*j + lr    ) * VSTR + 8*n + lq];
                bf[1] = Vs[(8*j + lr + 4) * VSTR + 8*n + lq];
                mma_tf32(o[n], pa, bf);
            }
        }
    }

    // Epilogue: normalize, write g_att
    float inv0 = 1.f / l0r, inv1 = 1.f / l1r;
    float* Og = g_att + (size_t)(b*SEQ + q0 + R0 + lq) * DIMN + h * HD;
    #pragma unroll
    for (int n = 0; n < 16; n++) {
        int col = 8*n + 2*lr;
        *(float2*)(Og + col) = make_float2(o[n][0]*inv0, o[n][1]*inv0);
        *(float2*)(Og + (size_t)8 * DIMN + col) = make_float2(o[n][2]*inv1, o[n][3]*inv1);
    }
}

// ---------------------------------------------------------------------------
// Launch
// ---------------------------------------------------------------------------
extern "C" void kernel_launch(void* const* d_in, const int* in_sizes, int n_in,
                              void* d_out, int out_size)
{
    const float* x  = (const float*)d_in[0];
    const float* fc = (const float*)d_in[2];
    const float* fs = (const float*)d_in[3];
    const float* wq = (const float*)d_in[5];
    const float* wk = (const float*)d_in[6];
    const float* wv = (const float*)d_in[7];
    const float* wo = (const float*)d_in[8];
    float* out = (float*)d_out;

    float *q, *k, *v, *att;
    cudaGetSymbolAddress((void**)&q,   g_q);
    cudaGetSymbolAddress((void**)&k,   g_k);
    cudaGetSymbolAddress((void**)&v,   g_v);
    cudaGetSymbolAddress((void**)&att, g_att);

    cudaFuncSetAttribute(attn_tc,
                         cudaFuncAttributeMaxDynamicSharedMemorySize, AT_SMEM);

    dim3 gg(DIMN/128, ROWS/128);   // (16, 32)
    gemm_tf32<<<gg, 256>>>(x, wq, q, ROWS, DIMN, DIMN);
    gemm_tf32<<<gg, 256>>>(x, wk, k, ROWS, DIMN, DIMN);
    gemm_tf32<<<gg, 256>>>(x, wv, v, ROWS, DIMN, DIMN);

    rope_kernel<<<(ROWS*1024)/256, 256>>>(q, k, fc, fs);

    dim3 ga(SEQ/128, NH, BSZ);     // (16, 16, 2)
    attn_tc<<<ga, 256, AT_SMEM>>>();

    gemm_tf32<<<gg, 256>>>(att, wo, out, ROWS, DIMN, DIMN);
}

// round 8
// speedup vs baseline: 3.3919x; 1.1248x over previous
#include <cuda_runtime.h>
#include <math.h>

#define DIMN 2048
#define NH   16
#define HD   128
#define BSZ  2
#define SEQ  2048
#define ROWS (BSZ*SEQ)   // 4096

// Scratch buffers (allocation-free rule: __device__ globals)
__device__ float g_q[ROWS*DIMN];
__device__ float g_k[ROWS*DIMN];
__device__ float g_v[ROWS*DIMN];
__device__ float g_att[ROWS*DIMN];

__device__ __forceinline__ unsigned f2tf32(float x) {
    unsigned r;
    asm("cvt.rna.tf32.f32 %0, %1;" : "=r"(r) : "f"(x));
    return r;
}

__device__ __forceinline__ void mma_tf32(float c[4],
                                         const unsigned a[4],
                                         const unsigned b[2]) {
    asm("mma.sync.aligned.m16n8k8.row.col.f32.tf32.tf32.f32 "
        "{%0,%1,%2,%3}, {%4,%5,%6,%7}, {%8,%9}, {%0,%1,%2,%3};"
        : "+f"(c[0]), "+f"(c[1]), "+f"(c[2]), "+f"(c[3])
        : "r"(a[0]), "r"(a[1]), "r"(a[2]), "r"(a[3]),
          "r"(b[0]), "r"(b[1]));
}

// ---------------------------------------------------------------------------
// TF32 tensor-core GEMM body: C[M,N] = A[M,K] * B[N,K]^T
// 128x128 tile, BK=32, 256 threads, DOUBLE-BUFFERED smem (1 sync/stage).
// ---------------------------------------------------------------------------
#define BM 128
#define BN 128
#define BK 32
#define GSTR (BK + 4)                    // 36 words/row
#define GBUF (128 * GSTR)                // words per buffer
#define GSMEM (4 * GBUF * 4)             // 2 bufs x (A+B) = 73728 bytes

__device__ __forceinline__ void gemm_body(const float* __restrict__ A,
                                          const float* __restrict__ B,
                                          float* __restrict__ C,
                                          int N, int K,
                                          unsigned* __restrict__ sm)
{
    unsigned* As = sm;                   // [2][128][GSTR]
    unsigned* Bs = sm + 2 * GBUF;

    const int tid  = threadIdx.x;
    const int wid  = tid >> 5;
    const int lane = tid & 31;
    const int lq   = lane >> 2;
    const int lr   = lane & 3;
    const int wm   = (wid >> 2) * 64;
    const int wn   = (wid & 3) * 32;
    const int m0   = blockIdx.y * BM;
    const int n0   = blockIdx.x * BN;
    const int lrow = tid >> 3;           // 0..31
    const int lc4  = (tid & 7) * 4;      // 0..28

    float c[4][4][4];
    #pragma unroll
    for (int mt = 0; mt < 4; mt++)
        #pragma unroll
        for (int nt = 0; nt < 4; nt++)
            #pragma unroll
            for (int r = 0; r < 4; r++) c[mt][nt][r] = 0.f;

    const float* Ap = A + (size_t)(m0 + lrow) * K + lc4;
    const float* Bp = B + (size_t)(n0 + lrow) * K + lc4;

    float4 ra[4], rb[4];
    #pragma unroll
    for (int it = 0; it < 4; it++) {
        ra[it] = *(const float4*)(Ap + (size_t)(it * 32) * K);
        rb[it] = *(const float4*)(Bp + (size_t)(it * 32) * K);
    }
    // store stage 0 into buffer 0
    #pragma unroll
    for (int it = 0; it < 4; it++) {
        int row = it * 32 + lrow;
        *(uint4*)&As[row * GSTR + lc4] =
            make_uint4(f2tf32(ra[it].x), f2tf32(ra[it].y), f2tf32(ra[it].z), f2tf32(ra[it].w));
        *(uint4*)&Bs[row * GSTR + lc4] =
            make_uint4(f2tf32(rb[it].x), f2tf32(rb[it].y), f2tf32(rb[it].z), f2tf32(rb[it].w));
    }

    const int NST = K / BK;
    for (int i = 0; i < NST; i++) {
        const int bsel = (i & 1) * GBUF;

        if (i + 1 < NST) {
            const int koff = (i + 1) * BK;
            #pragma unroll
            for (int it = 0; it < 4; it++) {
                ra[it] = *(const float4*)(Ap + (size_t)(it * 32) * K + koff);
                rb[it] = *(const float4*)(Bp + (size_t)(it * 32) * K + koff);
            }
        }

        __syncthreads();   // buffer bsel fully written; prior reads of other buf done

        #pragma unroll
        for (int ks = 0; ks < 4; ks++) {
            const int kb = ks * 8;
            unsigned af[4][4], bf[4][2];
            #pragma unroll
            for (int mt = 0; mt < 4; mt++) {
                int r = wm + mt * 16;
                af[mt][0] = As[bsel + (r + lq    ) * GSTR + kb + lr    ];
                af[mt][1] = As[bsel + (r + lq + 8) * GSTR + kb + lr    ];
                af[mt][2] = As[bsel + (r + lq    ) * GSTR + kb + lr + 4];
                af[mt][3] = As[bsel + (r + lq + 8) * GSTR + kb + lr + 4];
            }
            #pragma unroll
            for (int nt = 0; nt < 4; nt++) {
                int cn = wn + nt * 8;
                bf[nt][0] = Bs[bsel + (cn + lq) * GSTR + kb + lr    ];
                bf[nt][1] = Bs[bsel + (cn + lq) * GSTR + kb + lr + 4];
            }
            #pragma unroll
            for (int mt = 0; mt < 4; mt++)
                #pragma unroll
                for (int nt = 0; nt < 4; nt++)
                    mma_tf32(c[mt][nt], af[mt], bf[nt]);
        }

        if (i + 1 < NST) {
            const int osel = ((i + 1) & 1) * GBUF;
            #pragma unroll
            for (int it = 0; it < 4; it++) {
                int row = it * 32 + lrow;
                *(uint4*)&As[osel + row * GSTR + lc4] =
                    make_uint4(f2tf32(ra[it].x), f2tf32(ra[it].y), f2tf32(ra[it].z), f2tf32(ra[it].w));
                *(uint4*)&Bs[osel + row * GSTR + lc4] =
                    make_uint4(f2tf32(rb[it].x), f2tf32(rb[it].y), f2tf32(rb[it].z), f2tf32(rb[it].w));
            }
        }
    }

    #pragma unroll
    for (int mt = 0; mt < 4; mt++) {
        int row = m0 + wm + mt * 16 + lq;
        #pragma unroll
        for (int nt = 0; nt < 4; nt++) {
            int col = n0 + wn + nt * 8 + lr * 2;
            *(float2*)(C + (size_t)row * N + col)       = make_float2(c[mt][nt][0], c[mt][nt][1]);
            *(float2*)(C + (size_t)(row + 8) * N + col) = make_float2(c[mt][nt][2], c[mt][nt][3]);
        }
    }
}

// Fused Q/K/V projection: blockIdx.z selects weight + destination.
__global__ __launch_bounds__(256, 1) void gemm_qkv(const float* __restrict__ x,
                                                   const float* __restrict__ wq,
                                                   const float* __restrict__ wk,
                                                   const float* __restrict__ wv)
{
    extern __shared__ unsigned gsm[];
    const float* B = (blockIdx.z == 0) ? wq : (blockIdx.z == 1) ? wk : wv;
    float*       C = (blockIdx.z == 0) ? g_q : (blockIdx.z == 1) ? g_k : g_v;
    gemm_body(x, B, C, DIMN, DIMN, gsm);
}

// Generic single GEMM (output projection).
__global__ __launch_bounds__(256, 1) void gemm_tf32(const float* __restrict__ A,
                                                    const float* __restrict__ B,
                                                    float* __restrict__ C,
                                                    int M, int N, int K)
{
    extern __shared__ unsigned gsm[];
    gemm_body(A, B, C, N, K, gsm);
}

// ---------------------------------------------------------------------------
// Tensor-core flash attention with FUSED RoPE on Q/K loads.
// 128-query tile per CTA, 8 warps, 64-key k-tiles. Q split hi+lo tf32.
// ---------------------------------------------------------------------------
#define KSTR 132
#define VSTR 136
#define AT_SMEM ((2*128*128 + 64*KSTR + 64*VSTR) * 4)

__global__ __launch_bounds__(256, 1) void attn_tc(const float* __restrict__ fc,
                                                  const float* __restrict__ fs)
{
    extern __shared__ unsigned sm[];
    unsigned* Qhi = sm;
    unsigned* Qlo = sm + 128*128;
    unsigned* Ks  = sm + 2*128*128;
    unsigned* Vs  = Ks + 64*KSTR;

    const int tid  = threadIdx.x;
    const int wid  = tid >> 5;
    const int lane = tid & 31;
    const int lq   = lane >> 2;
    const int lr   = lane & 3;
    const int qt   = gridDim.x - 1 - blockIdx.x;   // heavy tiles first
    const int h    = blockIdx.y;
    const int b    = blockIdx.z;
    const int q0   = qt * 128;
    const int R0   = wid * 16;

    const float* Qg = g_q + (size_t)(b*SEQ + q0) * DIMN + h * HD;
    const float* Kg = g_k + (size_t)(b*SEQ) * DIMN + h * HD;
    const float* Vg = g_v + (size_t)(b*SEQ) * DIMN + h * HD;

    const float qsc = 0.08838834764831845f;  // 1/sqrt(128)

    // Load Q tile (128x128), apply RoPE + scale, split tf32 hi/lo, swizzle
    #pragma unroll
    for (int it = 0; it < 16; it++) {
        int i  = it * 256 + tid;
        int r  = i >> 5;              // 0..127
        int c4 = (i & 31) * 4;        // 0..124
        float4 v = *(const float4*)(Qg + (size_t)r * DIMN + c4);
        int s = q0 + r;
        int p = c4 >> 1;              // first pair index (0..62)
        float c0 = fc[s*64 + p],     sn0 = fs[s*64 + p];
        float c1 = fc[s*64 + p + 1], sn1 = fs[s*64 + p + 1];
        float x0 = (v.x * c0 - v.y * sn0) * qsc;
        float y0 = (v.x * sn0 + v.y * c0) * qsc;
        float x1 = (v.z * c1 - v.w * sn1) * qsc;
        float y1 = (v.z * sn1 + v.w * c1) * qsc;
        unsigned h0 = f2tf32(x0), h1 = f2tf32(y0),
                 h2 = f2tf32(x1), h3 = f2tf32(y1);
        unsigned l0 = f2tf32(x0 - __uint_as_float(h0));
        unsigned l1 = f2tf32(y0 - __uint_as_float(h1));
        unsigned l2 = f2tf32(x1 - __uint_as_float(h2));
        unsigned l3 = f2tf32(y1 - __uint_as_float(h3));
        int blk = (c4 >> 2) ^ (r & 7);
        *(uint4*)&Qhi[r * 128 + blk * 4] = make_uint4(h0, h1, h2, h3);
        *(uint4*)&Qlo[r * 128 + blk * 4] = make_uint4(l0, l1, l2, l3);
    }

    float o[16][4];
    #pragma unroll
    for (int n = 0; n < 16; n++)
        #pragma unroll
        for (int r = 0; r < 4; r++) o[n][r] = 0.f;
    float m0r = -1e30f, m1r = -1e30f, l0r = 0.f, l1r = 0.f;

    const int nkt = 2 * qt + 2;
    for (int kt = 0; kt < nkt; kt++) {
        const int k0 = kt * 64;
        __syncthreads();

        // Load K (RoPE'd) and V tiles (64x128), tf32-convert
        #pragma unroll
        for (int it = 0; it < 8; it++) {
            int i  = it * 256 + tid;
            int r  = i >> 5;
            int c4 = (i & 31) * 4;
            float4 kv = *(const float4*)(Kg + (size_t)(k0 + r) * DIMN + c4);
            float4 vv = *(const float4*)(Vg + (size_t)(k0 + r) * DIMN + c4);
            int s = k0 + r;
            int p = c4 >> 1;
            float c0 = fc[s*64 + p],     sn0 = fs[s*64 + p];
            float c1 = fc[s*64 + p + 1], sn1 = fs[s*64 + p + 1];
            float x0 = kv.x * c0 - kv.y * sn0;
            float y0 = kv.x * sn0 + kv.y * c0;
            float x1 = kv.z * c1 - kv.w * sn1;
            float y1 = kv.z * sn1 + kv.w * c1;
            *(uint4*)&Ks[r * KSTR + c4] =
                make_uint4(f2tf32(x0), f2tf32(y0), f2tf32(x1), f2tf32(y1));
            *(uint4*)&Vs[r * VSTR + c4] =
                make_uint4(f2tf32(vv.x), f2tf32(vv.y), f2tf32(vv.z), f2tf32(vv.w));
        }
        __syncthreads();

        // S = Q K^T with Q = hi + lo
        float s[8][4];
        #pragma unroll
        for (int j = 0; j < 8; j++)
            #pragma unroll
            for (int r = 0; r < 4; r++) s[j][r] = 0.f;

        #pragma unroll
        for (int ks = 0; ks < 16; ks++) {
            unsigned ah[4], al[4];
            int rA = (R0 + lq) * 128;
            int rB = (R0 + lq + 8) * 128;
            int blk0 = ((2*ks    ) ^ lq) * 4 + lr;
            int blk1 = ((2*ks + 1) ^ lq) * 4 + lr;
            ah[0] = Qhi[rA + blk0]; ah[1] = Qhi[rB + blk0];
            ah[2] = Qhi[rA + blk1]; ah[3] = Qhi[rB + blk1];
            al[0] = Qlo[rA + blk0]; al[1] = Qlo[rB + blk0];
            al[2] = Qlo[rA + blk1]; al[3] = Qlo[rB + blk1];
            #pragma unroll
            for (int j = 0; j < 8; j++) {
                unsigned bf[2];
                bf[0] = Ks[(8*j + lq) * KSTR + 8*ks + lr    ];
                bf[1] = Ks[(8*j + lq) * KSTR + 8*ks + lr + 4];
                mma_tf32(s[j], ah, bf);
                mma_tf32(s[j], al, bf);
            }
        }

        if (kt >= 2 * qt) {
            int grow0 = q0 + R0 + lq;
            int grow1 = grow0 + 8;
            #pragma unroll
            for (int j = 0; j < 8; j++) {
                int gc = k0 + 8*j + 2*lr;
                if (gc     > grow0) s[j][0] = -1e30f;
                if (gc + 1 > grow0) s[j][1] = -1e30f;
                if (gc     > grow1) s[j][2] = -1e30f;
                if (gc + 1 > grow1) s[j][3] = -1e30f;
            }
        }

        float mx0 = -1e30f, mx1 = -1e30f;
        #pragma unroll
        for (int j = 0; j < 8; j++) {
            mx0 = fmaxf(mx0, fmaxf(s[j][0], s[j][1]));
            mx1 = fmaxf(mx1, fmaxf(s[j][2], s[j][3]));
        }
        mx0 = fmaxf(mx0, __shfl_xor_sync(0xffffffffu, mx0, 1));
        mx0 = fmaxf(mx0, __shfl_xor_sync(0xffffffffu, mx0, 2));
        mx1 = fmaxf(mx1, __shfl_xor_sync(0xffffffffu, mx1, 1));
        mx1 = fmaxf(mx1, __shfl_xor_sync(0xffffffffu, mx1, 2));

        float mn0 = fmaxf(m0r, mx0), mn1 = fmaxf(m1r, mx1);
        float f0 = __expf(m0r - mn0), f1 = __expf(m1r - mn1);
        m0r = mn0; m1r = mn1;

        #pragma unroll
        for (int n = 0; n < 16; n++) {
            o[n][0] *= f0; o[n][1] *= f0;
            o[n][2] *= f1; o[n][3] *= f1;
        }

        float sum0 = 0.f, sum1 = 0.f;
        #pragma unroll
        for (int j = 0; j < 8; j++) {
            s[j][0] = __expf(s[j][0] - mn0);
            s[j][1] = __expf(s[j][1] - mn0);
            s[j][2] = __expf(s[j][2] - mn1);
            s[j][3] = __expf(s[j][3] - mn1);
            sum0 += s[j][0] + s[j][1];
            sum1 += s[j][2] + s[j][3];
        }
        sum0 += __shfl_xor_sync(0xffffffffu, sum0, 1);
        sum0 += __shfl_xor_sync(0xffffffffu, sum0, 2);
        sum1 += __shfl_xor_sync(0xffffffffu, sum1, 1);
        sum1 += __shfl_xor_sync(0xffffffffu, sum1, 2);
        l0r = l0r * f0 + sum0;
        l1r = l1r * f1 + sum1;

        // O += P V : P acc->A frag via shfl
        const int srcA = lq * 4 + (lr >> 1);
        const int srcB = srcA + 2;
        const bool odd = (lr & 1);
        #pragma unroll
        for (int j = 0; j < 8; j++) {
            float t0 = __shfl_sync(0xffffffffu, s[j][0], srcA);
            float t1 = __shfl_sync(0xffffffffu, s[j][1], srcA);
            float t2 = __shfl_sync(0xffffffffu, s[j][2], srcA);
            float t3 = __shfl_sync(0xffffffffu, s[j][3], srcA);
            float u0 = __shfl_sync(0xffffffffu, s[j][0], srcB);
            float u1 = __shfl_sync(0xffffffffu, s[j][1], srcB);
            float u2 = __shfl_sync(0xffffffffu, s[j][2], srcB);
            float u3 = __shfl_sync(0xffffffffu, s[j][3], srcB);
            unsigned pa[4];
            pa[0] = f2tf32(odd ? t1 : t0);
            pa[1] = f2tf32(odd ? t3 : t2);
            pa[2] = f2tf32(odd ? u1 : u0);
            pa[3] = f2tf32(odd ? u3 : u2);
            #pragma unroll
            for (int n = 0; n < 16; n++) {
                unsigned bf[2];
                bf[0] = Vs[(8*j + lr    ) * VSTR + 8*n + lq];
                bf[1] = Vs[(8*j + lr + 4) * VSTR + 8*n + lq];
                mma_tf32(o[n], pa, bf);
            }
        }
    }

    float inv0 = 1.f / l0r, inv1 = 1.f / l1r;
    float* Og = g_att + (size_t)(b*SEQ + q0 + R0 + lq) * DIMN + h * HD;
    #pragma unroll
    for (int n = 0; n < 16; n++) {
        int col = 8*n + 2*lr;
        *(float2*)(Og + col) = make_float2(o[n][0]*inv0, o[n][1]*inv0);
        *(float2*)(Og + (size_t)8 * DIMN + col) = make_float2(o[n][2]*inv1, o[n][3]*inv1);
    }
}

// ---------------------------------------------------------------------------
// Launch
// ---------------------------------------------------------------------------
extern "C" void kernel_launch(void* const* d_in, const int* in_sizes, int n_in,
                              void* d_out, int out_size)
{
    const float* x  = (const float*)d_in[0];
    const float* fc = (const float*)d_in[2];
    const float* fs = (const float*)d_in[3];
    const float* wq = (const float*)d_in[5];
    const float* wk = (const float*)d_in[6];
    const float* wv = (const float*)d_in[7];
    const float* wo = (const float*)d_in[8];
    float* out = (float*)d_out;

    float* att;
    cudaGetSymbolAddress((void**)&att, g_att);

    cudaFuncSetAttribute(gemm_qkv,
                         cudaFuncAttributeMaxDynamicSharedMemorySize, GSMEM);
    cudaFuncSetAttribute(gemm_tf32,
                         cudaFuncAttributeMaxDynamicSharedMemorySize, GSMEM);
    cudaFuncSetAttribute(attn_tc,
                         cudaFuncAttributeMaxDynamicSharedMemorySize, AT_SMEM);

    dim3 gq(DIMN/128, ROWS/128, 3);    // (16, 32, 3)
    gemm_qkv<<<gq, 256, GSMEM>>>(x, wq, wk, wv);

    dim3 ga(SEQ/128, NH, BSZ);         // (16, 16, 2)
    attn_tc<<<ga, 256, AT_SMEM>>>(fc, fs);

    dim3 gg(DIMN/128, ROWS/128);       // (16, 32)
    gemm_tf32<<<gg, 256, GSMEM>>>(att, wo, out, ROWS, DIMN, DIMN);
}